// round 14
// baseline (speedup 1.0000x reference)
#include <cuda_runtime.h>
#include <cuda_bf16.h>
#include <cstdint>

// Problem shapes (fixed by setup_inputs)
#define B_      4
#define L_      8192
#define BLOCK_  128
#define NB_     (L_ / BLOCK_)          // 64
#define V_      32000
#define D_      1024
#define NT_     (L_ + NB_)             // 8256 new_tokens per batch row

// Output layout (flattened tuple, row-major, float32):
//   [0,        B*NT)                new_tokens      (33024)
//   [OFF_CE,   OFF_CE + B*NB*D)     cat_emb         (262144)
//   [OFF_H,    OFF_H  + B*NB*V)     hist            (8192000)
#define OFF_CE  (B_ * NT_)                         // 33024
#define OFF_H   (OFF_CE + B_ * NB_ * D_)           // 295168

#define SUBS    8                                  // eighth-slices per (b,j)
#define SF32    (V_ / SUBS)                        // 4000 bins per sub
#define SF4     (SF32 / 4)                         // 1000 float4 per sub
#define NWORDS  (SF32 / 32)                        // 125 bitmap words
#define NTHR    128
#define GRID_   (B_ * NB_ * SUBS)                  // 2048 CTAs, one wave

// streaming (evict-first) 128-bit store
__device__ __forceinline__ void stg_cs_v4(float* p, float4 v)
{
    asm volatile("st.global.cs.v4.f32 [%0], {%1,%2,%3,%4};"
                 :: "l"(p), "f"(v.x), "f"(v.y), "f"(v.z), "f"(v.w)
                 : "memory");
}

__device__ __forceinline__ float4 bits_to_f4(uint32_t w, int i)
{
    const uint32_t bits = (w >> ((i & 7) << 2)) & 0xFu;
    float4 v;
    v.x = (bits & 1u) ? 1.0f : 0.0f;
    v.y = (bits & 2u) ? 1.0f : 0.0f;
    v.z = (bits & 4u) ? 1.0f : 0.0f;
    v.w = (bits & 8u) ? 1.0f : 0.0f;
    return v;
}

// Bitmap histogram, fine-grained CTAs (16 KB drain each) + streaming stores.
// CTA (bj, s):
//   1. zero 125-word bitmap
//   2. atomicOr presence bits for tokens in this eighth's range
//      (exact duplicates -> overflow list)
//   3. drain: interleaved bitmap->float4 expansion, st.global.cs.v4
//   4. (s==0) new_tokens early; embed row prefetched pre-barrier,
//      stored post-drain.
__global__ __launch_bounds__(NTHR)
void chunk_agg_fine(const int* __restrict__ tokens,
                    const float* __restrict__ catW,
                    float* __restrict__ out)
{
    __shared__ uint32_t bm[NWORDS];      // 500 B
    __shared__ int      ov_tok[BLOCK_];  // duplicate rel-bins
    __shared__ int      ov_cnt;

    const int bid = blockIdx.x;
    const int s   = bid & (SUBS - 1);
    const int bj  = bid >> 3;            // 0..255
    const int b   = bj >> 6;
    const int j   = bj & 63;
    const int tid = threadIdx.x;

    const int* __restrict__ blk = tokens + b * L_ + j * BLOCK_;

    // every thread owns one token of the block (NTHR == BLOCK_)
    const int mytok = blk[tid];

    // ---- 1) zero bitmap + counter
    if (tid < NWORDS) bm[tid] = 0u;
    if (tid == 0)     ov_cnt = 0;

    // ---- new_tokens (fire-and-forget scalar stores, s==0 only)
    if (s == 0) {
        out[b * NT_ + NB_ + j * BLOCK_ + tid] = (float)mytok;
        if (tid == 0)
            out[b * NT_ + j] = (float)mytok;
    }

    __syncthreads();

    // ---- 2) presence bits + exact duplicate list
    {
        const int lo = s * SF32;
        if (mytok >= lo && mytok < lo + SF32) {
            const int rel = mytok - lo;
            const uint32_t mask = 1u << (rel & 31);
            const uint32_t old  = atomicOr(&bm[rel >> 5], mask);
            if (old & mask) {
                const int k = atomicAdd(&ov_cnt, 1);
                ov_tok[k] = rel;
            }
        }
    }

    // ---- embed-row prefetch (s==0): two float4 per thread (D=1024, 128 thr)
    float4 emb0 = make_float4(0.f, 0.f, 0.f, 0.f);
    float4 emb1 = emb0;
    if (s == 0) {
        const int t0 = __shfl_sync(0xFFFFFFFFu, mytok, 0) ;
        // t0 must be token 0 of the block for ALL warps: broadcast via blk[0]
        const int tok0 = blk[0];
        (void)t0;
        const float4* src = reinterpret_cast<const float4*>(catW + (size_t)tok0 * D_);
        emb0 = src[tid];
        emb1 = src[tid + NTHR];
    }

    __syncthreads();

    // ---- 3) drain: 1000 float4, interleaved schedule, streaming stores
    float* __restrict__ histq = out + OFF_H + (size_t)bj * V_ + s * SF32;
    const int novf = ov_cnt;

    if (novf == 0) {
        #pragma unroll 8
        for (int i = tid; i < SF4; i += NTHR)
            stg_cs_v4(histq + i * 4, bits_to_f4(bm[i >> 3], i));
    } else {
        #pragma unroll 4
        for (int i = tid; i < SF4; i += NTHR) {
            float4 v = bits_to_f4(bm[i >> 3], i);
            for (int e = 0; e < novf; ++e) {
                const int rel = ov_tok[e];
                if ((rel >> 2) == i) {
                    switch (rel & 3) {
                        case 0: v.x += 1.0f; break;
                        case 1: v.y += 1.0f; break;
                        case 2: v.z += 1.0f; break;
                        default: v.w += 1.0f; break;
                    }
                }
            }
            stg_cs_v4(histq + i * 4, v);
        }
    }

    // ---- embed-row store (prefetched above)
    if (s == 0) {
        float4* dst = reinterpret_cast<float4*>(out + OFF_CE + bj * D_);
        dst[tid]        = emb0;
        dst[tid + NTHR] = emb1;
    }
}

extern "C" void kernel_launch(void* const* d_in, const int* in_sizes, int n_in,
                              void* d_out, int out_size)
{
    const int*   tokens = (const int*)  d_in[0];   // [4, 8192] int32
    const float* catW   = (const float*)d_in[1];   // [32000, 1024] f32
    // d_in[2] (num_embed_W) is a dead lookup in the reference — unused.
    float* out = (float*)d_out;

    chunk_agg_fine<<<GRID_, NTHR>>>(tokens, catW, out);
}